// round 16
// baseline (speedup 1.0000x reference)
#include <cuda_runtime.h>
#include <cuda_bf16.h>
#include <cuda_fp16.h>
#include <math_constants.h>
#include <cstdint>

#define BATCH 4
#define SEQ   2048
#define DIM   1024

#define BM 128
#define BN 128
#define BK 64
#define THREADS 128
#define STAGES 3
#define A_STAGE_BYTES 18432u
#define STAGE_BYTES   36864u
#define SMEM_TOTAL (STAGES * STAGE_BYTES)   // 110592 -> 2 CTA/SM

// pipeline split: scores tiles [0, TSPLIT) cover row blocks [0, BYSPLIT)
#define BYSPLIT 11
#define TSPLIT  (BYSPLIT * (BYSPLIT + 1) / 2)   // 66
#define NTILES  136
#define ROWSPLIT (BYSPLIT * BM)                 // 1408

// ---------------- scratch ----------------
__device__ __half g_xh [(long)BATCH * SEQ * DIM];
__device__ __half g_Wqh[(long)DIM * DIM];
__device__ __half g_Wkh[(long)DIM * DIM];
__device__ __half g_Wvh[(long)DIM * DIM];
__device__ __half g_Qh [(long)BATCH * SEQ * DIM];
__device__ __half g_Kh [(long)BATCH * SEQ * DIM];
__device__ __half g_Vh [(long)BATCH * SEQ * DIM];
__device__ float  g_S  [(long)BATCH * SEQ * SEQ];
__device__ __half g_Ph [(long)BATCH * SEQ * SEQ];

// ---------------- asm helpers ----------------
__device__ __forceinline__ uint32_t smem_u32(const void* p) {
    uint32_t a;
    asm("{ .reg .u64 t; cvta.to.shared.u64 t, %1; cvt.u32.u64 %0, t; }" : "=r"(a) : "l"(p));
    return a;
}
#define LDMX4(r0,r1,r2,r3,addr) \
    asm volatile("ldmatrix.sync.aligned.m8n8.x4.shared.b16 {%0,%1,%2,%3}, [%4];" \
                 : "=r"(r0),"=r"(r1),"=r"(r2),"=r"(r3) : "r"(addr))
#define LDMX4T(r0,r1,r2,r3,addr) \
    asm volatile("ldmatrix.sync.aligned.m8n8.x4.trans.shared.b16 {%0,%1,%2,%3}, [%4];" \
                 : "=r"(r0),"=r"(r1),"=r"(r2),"=r"(r3) : "r"(addr))
#define MMAH(c,a,b0,b1) \
    asm volatile("mma.sync.aligned.m16n8k16.row.col.f32.f16.f16.f32 " \
                 "{%0,%1,%2,%3}, {%4,%5,%6,%7}, {%8,%9}, {%0,%1,%2,%3};" \
                 : "+f"((c)[0]),"+f"((c)[1]),"+f"((c)[2]),"+f"((c)[3]) \
                 : "r"((a)[0]),"r"((a)[1]),"r"((a)[2]),"r"((a)[3]),"r"(b0),"r"(b1))
#define CPASYNC(s,g) \
    asm volatile("cp.async.cg.shared.global [%0], [%1], 16;" :: "r"(s),"l"(g))
#define CP_COMMIT() asm volatile("cp.async.commit_group;" ::: "memory")
#define CP_WAIT(N)  asm volatile("cp.async.wait_group %0;" :: "n"(N) : "memory")

// ---------------- input conversions: fp32 -> plain fp16 ----------------
__global__ void convert_f16(const float4* __restrict__ in, uint2* __restrict__ out, long n4) {
    long i = (long)blockIdx.x * blockDim.x + threadIdx.x;
    if (i >= n4) return;
    float4 v = in[i];
    unsigned short h0 = __half_as_ushort(__float2half_rn(v.x));
    unsigned short h1 = __half_as_ushort(__float2half_rn(v.y));
    unsigned short h2 = __half_as_ushort(__float2half_rn(v.z));
    unsigned short h3 = __half_as_ushort(__float2half_rn(v.w));
    uint2 u;
    u.x = (uint32_t)h0 | ((uint32_t)h1 << 16);
    u.y = (uint32_t)h2 | ((uint32_t)h3 << 16);
    out[i] = u;
}

__global__ void convert_w3(const float4* __restrict__ wq, const float4* __restrict__ wk,
                           const float4* __restrict__ wv,
                           uint2* __restrict__ oq, uint2* __restrict__ ok,
                           uint2* __restrict__ ov, long n4) {
    long i = (long)blockIdx.x * blockDim.x + threadIdx.x;
    if (i >= n4) return;
    const float4* in = (blockIdx.y == 0) ? wq : (blockIdx.y == 1) ? wk : wv;
    uint2* out = (blockIdx.y == 0) ? oq : (blockIdx.y == 1) ? ok : ov;
    float4 v = in[i];
    unsigned short h0 = __half_as_ushort(__float2half_rn(v.x));
    unsigned short h1 = __half_as_ushort(__float2half_rn(v.y));
    unsigned short h2 = __half_as_ushort(__float2half_rn(v.z));
    unsigned short h3 = __half_as_ushort(__float2half_rn(v.w));
    uint2 u;
    u.x = (uint32_t)h0 | ((uint32_t)h1 << 16);
    u.y = (uint32_t)h2 | ((uint32_t)h3 << 16);
    out[i] = u;
}

// ================= GEMM engine (4 warps, 64x64 warptile) =================
#define LOADFRAG_NT(aoff, boff, ks, buf)                                                \
    {                                                                                   \
        _Pragma("unroll")                                                               \
        for (int mi = 0; mi < 4; mi++)                                                  \
            LDMX4(af[buf][mi][0], af[buf][mi][1], af[buf][mi][2], af[buf][mi][3],       \
                  (aoff) + (uint32_t)(((wm2 * 64 + mi * 16 + l15) * 72 + lh * 8 + (ks) * 16) * 2)); \
        _Pragma("unroll")                                                               \
        for (int j2 = 0; j2 < 4; j2++)                                                  \
            LDMX4(bf[buf][j2][0], bf[buf][j2][1], bf[buf][j2][2], bf[buf][j2][3],       \
                  (boff) + (uint32_t)(((wn2 * 64 + j2 * 16 + l15) * 72 + lh * 8 + (ks) * 16) * 2)); \
    }

#define LOADFRAG_NN(aoff, boff, ks, buf)                                                \
    {                                                                                   \
        _Pragma("unroll")                                                               \
        for (int mi = 0; mi < 4; mi++)                                                  \
            LDMX4(af[buf][mi][0], af[buf][mi][1], af[buf][mi][2], af[buf][mi][3],       \
                  (aoff) + (uint32_t)(((wm2 * 64 + mi * 16 + l15) * 72 + lh * 8 + (ks) * 16) * 2)); \
        _Pragma("unroll")                                                               \
        for (int j2 = 0; j2 < 4; j2++)                                                  \
            LDMX4T(bf[buf][j2][0], bf[buf][j2][1], bf[buf][j2][2], bf[buf][j2][3],      \
                  (boff) + (uint32_t)((((ks) * 16 + l15) * 136 + wn2 * 64 + j2 * 16 + lh * 8) * 2)); \
    }

#define COMPUTE_BODY(LOADFRAG, MOP, B0A, B0B, B1A, B1B)                                 \
    {                                                                                   \
        uint32_t af[2][4][4], bf[2][4][4];                                              \
        LOADFRAG(aoff_, boff_, 0, 0);                                                   \
        _Pragma("unroll")                                                               \
        for (int ks = 0; ks < 4; ks++) {                                                \
            const int cur = ks & 1;                                                     \
            if (ks < 3) LOADFRAG(aoff_, boff_, ks + 1, cur ^ 1);                        \
            _Pragma("unroll")                                                           \
            for (int mi = 0; mi < 4; mi++) {                                            \
                _Pragma("unroll")                                                       \
                for (int j2 = 0; j2 < 4; j2++) {                                        \
                    MOP(acc[mi][2*j2],   af[cur][mi], bf[cur][j2][B0A], bf[cur][j2][B0B]); \
                    MOP(acc[mi][2*j2+1], af[cur][mi], bf[cur][j2][B1A], bf[cur][j2][B1B]); \
                }                                                                       \
            }                                                                           \
        }                                                                               \
    }

#define COMPUTE_NT_H() COMPUTE_BODY(LOADFRAG_NT, MMAH, 0, 2, 1, 3)
#define COMPUTE_NN_H() COMPUTE_BODY(LOADFRAG_NN, MMAH, 0, 1, 2, 3)

#define MAINLOOP(NTtiles, LOADFN, COMPUTE_MACRO)                                        \
    LOADFN(0, 0);                                                                       \
    LOADFN(1, 1);                                                                       \
    {                                                                                   \
        int cs = 0;                                                                     \
        for (int t = 0; t < (NTtiles); t++) {                                           \
            if (t + 2 < (NTtiles)) { CP_WAIT(1); } else { CP_WAIT(0); }                 \
            __syncthreads();                                                            \
            int ldst = cs + 2; if (ldst >= 3) ldst -= 3;                                \
            if (t + 2 < (NTtiles)) LOADFN(t + 2, ldst);                                 \
            const uint32_t aoff_ = sbase + (uint32_t)cs * STAGE_BYTES;                  \
            const uint32_t boff_ = aoff_ + A_STAGE_BYTES;                               \
            COMPUTE_MACRO();                                                            \
            cs = (cs == 2) ? 0 : cs + 1;                                                \
        }                                                                               \
    }

#define ACC_DECL                                                                        \
    float acc[4][8][4];                                                                 \
    _Pragma("unroll")                                                                   \
    for (int i = 0; i < 4; i++)                                                         \
        _Pragma("unroll")                                                               \
        for (int j = 0; j < 8; j++)                                                     \
            _Pragma("unroll")                                                           \
            for (int r = 0; r < 4; r++) acc[i][j][r] = 0.f;

// ---------------- projection GEMM: plain fp16, K=1024 ----------------
__global__ void __launch_bounds__(THREADS, 2)
proj_gemm(const __half* __restrict__ A,
          const __half* __restrict__ Wq, const __half* __restrict__ Wk,
          const __half* __restrict__ Wv,
          __half* __restrict__ Qo, __half* __restrict__ Ko,
          __half* __restrict__ Vo, int wsel_base)
{
    extern __shared__ char smem[];
    const uint32_t sbase = smem_u32(smem);

    const int wsel = wsel_base + (blockIdx.x >> 3);
    const __half* B = (wsel == 0) ? Wq : (wsel == 1) ? Wk : Wv;
    __half* Co = (wsel == 0) ? Qo : (wsel == 1) ? Ko : Vo;

    const int tid = threadIdx.x, lid = tid & 31, wid = tid >> 5;
    const int wm2 = wid & 1, wn2 = wid >> 1;
    const int row0 = blockIdx.y * BM, col0 = (blockIdx.x & 7) * BN;
    const int nT = DIM / BK;   // 16

    ACC_DECL;

    auto LOAD = [&](int t, int st) {
        const long kt = (long)t * BK;
        const uint32_t aoff = sbase + (uint32_t)st * STAGE_BYTES;
        const uint32_t boff = aoff + A_STAGE_BYTES;
        #pragma unroll
        for (int i = 0; i < 8; i++) {
            int idx = tid + i * THREADS;
            int row = idx >> 3, q = idx & 7;
            CPASYNC(aoff + (uint32_t)(row * 144 + q * 16),
                    A + (long)(row0 + row) * DIM + kt + q * 8);
            CPASYNC(boff + (uint32_t)(row * 144 + q * 16),
                    B + (long)(col0 + row) * DIM + kt + q * 8);
        }
        CP_COMMIT();
    };

    const int l15 = lid & 15, lh = lid >> 4;

    MAINLOOP(nT, LOAD, COMPUTE_NT_H);

    const int g = lid >> 2, tig = lid & 3;
    #pragma unroll
    for (int mi = 0; mi < 4; mi++) {
        #pragma unroll
        for (int j = 0; j < 8; j++) {
            const int c = col0 + wn2 * 64 + j * 8 + 2 * tig;
            #pragma unroll
            for (int s = 0; s < 2; s++) {
                const int r = row0 + wm2 * 64 + mi * 16 + g + s * 8;
                unsigned short h0 = __half_as_ushort(__float2half_rn(acc[mi][j][2*s]));
                unsigned short h1 = __half_as_ushort(__float2half_rn(acc[mi][j][2*s+1]));
                *reinterpret_cast<uint32_t*>(Co + (long)r * DIM + c) =
                    (uint32_t)h0 | ((uint32_t)h1 << 16);
            }
        }
    }
}

// ---------------- scores GEMM: tile range [t_base, t_base + gridDim.x) ----------------
__global__ void __launch_bounds__(THREADS, 2)
scores_gemm(const __half* __restrict__ Q, const __half* __restrict__ Kk,
            float* __restrict__ Sc, float alpha, int t_base)
{
    extern __shared__ char smem[];
    const uint32_t sbase = smem_u32(smem);

    int t_lin = t_base + blockIdx.x;
    int by = (int)((sqrtf(8.f * t_lin + 1.f) - 1.f) * 0.5f);
    while ((by + 1) * (by + 2) / 2 <= t_lin) by++;
    while (by * (by + 1) / 2 > t_lin) by--;
    const int bx = t_lin - by * (by + 1) / 2;

    const __half* A = Q  + (long)blockIdx.z * SEQ * DIM;
    const __half* B = Kk + (long)blockIdx.z * SEQ * DIM;
    float* C = Sc + (long)blockIdx.z * SEQ * SEQ;

    const int tid = threadIdx.x, lid = tid & 31, wid = tid >> 5;
    const int wm2 = wid & 1, wn2 = wid >> 1;
    const int row0 = by * BM, col0 = bx * BN;
    const int nT = DIM / BK;   // 16

    ACC_DECL;

    auto LOAD = [&](int t, int st) {
        const long kt = (long)t * BK;
        const uint32_t aoff = sbase + (uint32_t)st * STAGE_BYTES;
        const uint32_t boff = aoff + A_STAGE_BYTES;
        #pragma unroll
        for (int i = 0; i < 8; i++) {
            int idx = tid + i * THREADS;
            int row = idx >> 3, q = idx & 7;
            CPASYNC(aoff + (uint32_t)(row * 144 + q * 16),
                    A + (long)(row0 + row) * DIM + kt + q * 8);
            CPASYNC(boff + (uint32_t)(row * 144 + q * 16),
                    B + (long)(col0 + row) * DIM + kt + q * 8);
        }
        CP_COMMIT();
    };

    const int l15 = lid & 15, lh = lid >> 4;

    MAINLOOP(nT, LOAD, COMPUTE_NT_H);

    const int g = lid >> 2, tig = lid & 3;
    #pragma unroll
    for (int mi = 0; mi < 4; mi++) {
        #pragma unroll
        for (int j = 0; j < 8; j++) {
            const int c = col0 + wn2 * 64 + j * 8 + 2 * tig;
            #pragma unroll
            for (int s = 0; s < 2; s++) {
                const int r = row0 + wm2 * 64 + mi * 16 + g + s * 8;
                float2 o = make_float2(acc[mi][j][2*s] * alpha, acc[mi][j][2*s+1] * alpha);
                *reinterpret_cast<float2*>(&C[(long)r * SEQ + c]) = o;
            }
        }
    }
}

// ---------------- PV GEMM: row-block range [by0, by0 + gridDim.y) ----------------
__global__ void __launch_bounds__(THREADS, 2)
pv_gemm(const __half* __restrict__ P, const __half* __restrict__ V,
        float* __restrict__ Out, int by0)
{
    extern __shared__ char smem[];
    const uint32_t sbase = smem_u32(smem);

    const int by = by0 + (gridDim.y - 1 - blockIdx.y);   // longest K first
    const __half* A = P + (long)blockIdx.z * SEQ * SEQ;
    const __half* B = V + (long)blockIdx.z * SEQ * DIM;
    float* C = Out + (long)blockIdx.z * SEQ * DIM;

    const int tid = threadIdx.x, lid = tid & 31, wid = tid >> 5;
    const int wm2 = wid & 1, wn2 = wid >> 1;
    const int row0 = by * BM, col0 = blockIdx.x * BN;
    const int nT = (by + 1) * BM / BK;            // 2*(by+1) >= 2

    ACC_DECL;

    auto LOAD = [&](int t, int st) {
        const long kt = (long)t * BK;
        const uint32_t aoff = sbase + (uint32_t)st * STAGE_BYTES;
        const uint32_t boff = aoff + A_STAGE_BYTES;
        #pragma unroll
        for (int i = 0; i < 8; i++) {
            int idx = tid + i * THREADS;
            int row = idx >> 3, q = idx & 7;
            CPASYNC(aoff + (uint32_t)(row * 144 + q * 16),
                    A + (long)(row0 + row) * SEQ + kt + q * 8);
            int kr = idx >> 4, c = (idx & 15) * 8;
            CPASYNC(boff + (uint32_t)(kr * 272 + c * 2),
                    B + (long)(kt + kr) * DIM + col0 + c);
        }
        CP_COMMIT();
    };

    const int l15 = lid & 15, lh = lid >> 4;

    MAINLOOP(nT, LOAD, COMPUTE_NN_H);

    const int g = lid >> 2, tig = lid & 3;
    #pragma unroll
    for (int mi = 0; mi < 4; mi++) {
        #pragma unroll
        for (int j = 0; j < 8; j++) {
            const int c = col0 + wn2 * 64 + j * 8 + 2 * tig;
            #pragma unroll
            for (int s = 0; s < 2; s++) {
                const int r = row0 + wm2 * 64 + mi * 16 + g + s * 8;
                float2 o = make_float2(acc[mi][j][2*s], acc[mi][j][2*s+1]);
                *reinterpret_cast<float2*>(&C[(long)r * DIM + c]) = o;
            }
        }
    }
}

// ---------------- softmax (single global read): rows [r0, r0 + gridDim.x) ----------------
__global__ __launch_bounds__(256)
void softmax_p2(const float* __restrict__ Sc, const int* __restrict__ mask,
                __half* __restrict__ Ph, int r0)
{
    __shared__ float e[SEQ];
    __shared__ float red[256];
    const int q = r0 + (gridDim.x - 1 - blockIdx.x);   // longest rows first
    const int b = blockIdx.y, tid = threadIdx.x;
    const float* row = Sc + ((long)b * SEQ + q) * SEQ;
    const int* mk = mask + (long)b * SEQ;
    uint32_t* pr = reinterpret_cast<uint32_t*>(Ph + ((long)b * SEQ + q) * (long)SEQ);
    const int qe = ((q >> 7) + 1) << 7;    // block-aligned end

    // pass 1: single global read; cache raw scores (masked -> -inf) in smem, compute max
    float mx = -CUDART_INF_F;
    for (int c = tid; c <= q; c += 256) {
        float v = mk[c] ? row[c] : -CUDART_INF_F;
        e[c] = v;
        mx = fmaxf(mx, v);
    }
    for (int c = q + 1 + tid; c < qe; c += 256) e[c] = -CUDART_INF_F;
    red[tid] = mx; __syncthreads();
    #pragma unroll
    for (int s = 128; s > 0; s >>= 1) {
        if (tid < s) red[tid] = fmaxf(red[tid], red[tid + s]);
        __syncthreads();
    }
    mx = red[0]; __syncthreads();

    // pass 2 (smem only): exp + sum
    float sum = 0.f;
    for (int c = tid; c < qe; c += 256) {
        float v = __expf(e[c] - mx);     // exp(-inf - mx) = 0
        e[c] = v;
        sum += v;
    }
    red[tid] = sum; __syncthreads();
    #pragma unroll
    for (int s = 128; s > 0; s >>= 1) {
        if (tid < s) red[tid] += red[tid + s];
        __syncthreads();
    }
    const float inv = 1.f / red[0];
    __syncthreads();

    const int npair = qe >> 1;
    for (int t2 = tid; t2 < npair; t2 += 256) {
        unsigned short h0 = __half_as_ushort(__float2half_rn(e[2 * t2]     * inv));
        unsigned short h1 = __half_as_ushort(__float2half_rn(e[2 * t2 + 1] * inv));
        pr[t2] = (uint32_t)h0 | ((uint32_t)h1 << 16);
    }
}

// ---------------- host ----------------
extern "C" void kernel_launch(void* const* d_in, const int* in_sizes, int n_in,
                              void* d_out, int out_size)
{
    const float* x    = (const float*)d_in[0];
    const int*   mask = (const int*)  d_in[1];
    const float* Wq   = (const float*)d_in[2];
    const float* Wk   = (const float*)d_in[3];
    const float* Wv   = (const float*)d_in[4];
    float* out = (float*)d_out;

    __half *xp, *wqp, *wkp, *wvp, *qp, *kp, *vp, *pp;
    float* sp;
    cudaGetSymbolAddress((void**)&xp,  g_xh);
    cudaGetSymbolAddress((void**)&wqp, g_Wqh);
    cudaGetSymbolAddress((void**)&wkp, g_Wkh);
    cudaGetSymbolAddress((void**)&wvp, g_Wvh);
    cudaGetSymbolAddress((void**)&qp,  g_Qh);
    cudaGetSymbolAddress((void**)&kp,  g_Kh);
    cudaGetSymbolAddress((void**)&vp,  g_Vh);
    cudaGetSymbolAddress((void**)&sp,  g_S);
    cudaGetSymbolAddress((void**)&pp,  g_Ph);

    static cudaStream_t s2 = nullptr;
    static cudaEvent_t ev0 = nullptr, evA = nullptr, evB = nullptr, evEnd = nullptr;
    static bool init_done = false;
    if (!init_done) {
        cudaFuncSetAttribute(proj_gemm,   cudaFuncAttributeMaxDynamicSharedMemorySize, SMEM_TOTAL);
        cudaFuncSetAttribute(scores_gemm, cudaFuncAttributeMaxDynamicSharedMemorySize, SMEM_TOTAL);
        cudaFuncSetAttribute(pv_gemm,     cudaFuncAttributeMaxDynamicSharedMemorySize, SMEM_TOTAL);
        cudaStreamCreateWithFlags(&s2, cudaStreamNonBlocking);
        cudaEventCreateWithFlags(&ev0,   cudaEventDisableTiming);
        cudaEventCreateWithFlags(&evA,   cudaEventDisableTiming);
        cudaEventCreateWithFlags(&evB,   cudaEventDisableTiming);
        cudaEventCreateWithFlags(&evEnd, cudaEventDisableTiming);
        init_done = true;
    }

    const long nx4 = (long)BATCH * SEQ * DIM / 4;
    const long nw4 = (long)DIM * DIM / 4;
    convert_f16<<<(unsigned)((nx4 + 255) / 256), 256>>>((const float4*)x, (uint2*)xp, nx4);
    convert_w3<<<dim3((unsigned)((nw4 + 255) / 256), 3), 256>>>(
        (const float4*)Wq, (const float4*)Wk, (const float4*)Wv,
        (uint2*)wqp, (uint2*)wkp, (uint2*)wvp, nw4);

    // fork: V projection on side stream (s2 later hosts softmax+PV, so PV's
    // dependence on V is carried by stream order)
    cudaEventRecord(ev0, 0);
    cudaStreamWaitEvent(s2, ev0, 0);
    dim3 gV(8, (BATCH * SEQ) / BM, 1);
    proj_gemm<<<gV, THREADS, SMEM_TOTAL, s2>>>(xp, wqp, wkp, wvp, qp, kp, vp, 2);

    // main: QK projections
    dim3 gQK(16, (BATCH * SEQ) / BM, 1);
    proj_gemm<<<gQK, THREADS, SMEM_TOTAL>>>(xp, wqp, wkp, wvp, qp, kp, vp, 0);

    // scores half A: tiles [0, TSPLIT) -> row blocks [0, BYSPLIT)
    scores_gemm<<<dim3(TSPLIT, 1, BATCH), THREADS, SMEM_TOTAL>>>(qp, kp, sp, 1.f / 32.f, 0);
    cudaEventRecord(evA, 0);

    // scores half B: tiles [TSPLIT, NTILES)
    scores_gemm<<<dim3(NTILES - TSPLIT, 1, BATCH), THREADS, SMEM_TOTAL>>>(qp, kp, sp, 1.f / 32.f, TSPLIT);
    cudaEventRecord(evB, 0);

    // side stream: softmax + PV for half A (overlaps scores half B)
    cudaStreamWaitEvent(s2, evA, 0);
    softmax_p2<<<dim3(ROWSPLIT, BATCH), 256, 0, s2>>>(sp, mask, pp, 0);
    pv_gemm<<<dim3(DIM / BN, BYSPLIT, BATCH), THREADS, SMEM_TOTAL, s2>>>(pp, vp, out, 0);

    // side stream: softmax + PV for half B
    cudaStreamWaitEvent(s2, evB, 0);
    softmax_p2<<<dim3(SEQ - ROWSPLIT, BATCH), 256, 0, s2>>>(sp, mask, pp, ROWSPLIT);
    pv_gemm<<<dim3(DIM / BN, SEQ / BM - BYSPLIT, BATCH), THREADS, SMEM_TOTAL, s2>>>(pp, vp, out, BYSPLIT);

    // join
    cudaEventRecord(evEnd, s2);
    cudaStreamWaitEvent(0, evEnd, 0);
}

// round 17
// speedup vs baseline: 1.0291x; 1.0291x over previous
#include <cuda_runtime.h>
#include <cuda_bf16.h>
#include <cuda_fp16.h>
#include <math_constants.h>
#include <cstdint>

#define BATCH 4
#define SEQ   2048
#define DIM   1024

#define BM 128
#define BN 128
#define BK 64
#define THREADS 128
#define STAGES 3
#define A_STAGE_BYTES 18432u
#define STAGE_BYTES   36864u
#define SMEM_TOTAL (STAGES * STAGE_BYTES)   // 110592 -> 2 CTA/SM

// ---------------- scratch ----------------
__device__ __half g_xh [(long)BATCH * SEQ * DIM];
__device__ __half g_Wqh[(long)DIM * DIM];
__device__ __half g_Wkh[(long)DIM * DIM];
__device__ __half g_Wvh[(long)DIM * DIM];
__device__ __half g_Qh [(long)BATCH * SEQ * DIM];
__device__ __half g_Kh [(long)BATCH * SEQ * DIM];
__device__ __half g_Vh [(long)BATCH * SEQ * DIM];
__device__ float  g_S  [(long)BATCH * SEQ * SEQ];
__device__ __half g_Ph [(long)BATCH * SEQ * SEQ];

// ---------------- asm helpers ----------------
__device__ __forceinline__ uint32_t smem_u32(const void* p) {
    uint32_t a;
    asm("{ .reg .u64 t; cvta.to.shared.u64 t, %1; cvt.u32.u64 %0, t; }" : "=r"(a) : "l"(p));
    return a;
}
#define LDMX4(r0,r1,r2,r3,addr) \
    asm volatile("ldmatrix.sync.aligned.m8n8.x4.shared.b16 {%0,%1,%2,%3}, [%4];" \
                 : "=r"(r0),"=r"(r1),"=r"(r2),"=r"(r3) : "r"(addr))
#define LDMX4T(r0,r1,r2,r3,addr) \
    asm volatile("ldmatrix.sync.aligned.m8n8.x4.trans.shared.b16 {%0,%1,%2,%3}, [%4];" \
                 : "=r"(r0),"=r"(r1),"=r"(r2),"=r"(r3) : "r"(addr))
#define MMAH(c,a,b0,b1) \
    asm volatile("mma.sync.aligned.m16n8k16.row.col.f32.f16.f16.f32 " \
                 "{%0,%1,%2,%3}, {%4,%5,%6,%7}, {%8,%9}, {%0,%1,%2,%3};" \
                 : "+f"((c)[0]),"+f"((c)[1]),"+f"((c)[2]),"+f"((c)[3]) \
                 : "r"((a)[0]),"r"((a)[1]),"r"((a)[2]),"r"((a)[3]),"r"(b0),"r"(b1))
#define CPASYNC(s,g) \
    asm volatile("cp.async.cg.shared.global [%0], [%1], 16;" :: "r"(s),"l"(g))
#define CP_COMMIT() asm volatile("cp.async.commit_group;" ::: "memory")
#define CP_WAIT(N)  asm volatile("cp.async.wait_group %0;" :: "n"(N) : "memory")

// ---------------- input conversions: fp32 -> plain fp16 ----------------
__global__ void convert_f16(const float4* __restrict__ in, uint2* __restrict__ out, long n4) {
    long i = (long)blockIdx.x * blockDim.x + threadIdx.x;
    if (i >= n4) return;
    float4 v = in[i];
    unsigned short h0 = __half_as_ushort(__float2half_rn(v.x));
    unsigned short h1 = __half_as_ushort(__float2half_rn(v.y));
    unsigned short h2 = __half_as_ushort(__float2half_rn(v.z));
    unsigned short h3 = __half_as_ushort(__float2half_rn(v.w));
    uint2 u;
    u.x = (uint32_t)h0 | ((uint32_t)h1 << 16);
    u.y = (uint32_t)h2 | ((uint32_t)h3 << 16);
    out[i] = u;
}

__global__ void convert_w3(const float4* __restrict__ wq, const float4* __restrict__ wk,
                           const float4* __restrict__ wv,
                           uint2* __restrict__ oq, uint2* __restrict__ ok,
                           uint2* __restrict__ ov, long n4) {
    long i = (long)blockIdx.x * blockDim.x + threadIdx.x;
    if (i >= n4) return;
    const float4* in = (blockIdx.y == 0) ? wq : (blockIdx.y == 1) ? wk : wv;
    uint2* out = (blockIdx.y == 0) ? oq : (blockIdx.y == 1) ? ok : ov;
    float4 v = in[i];
    unsigned short h0 = __half_as_ushort(__float2half_rn(v.x));
    unsigned short h1 = __half_as_ushort(__float2half_rn(v.y));
    unsigned short h2 = __half_as_ushort(__float2half_rn(v.z));
    unsigned short h3 = __half_as_ushort(__float2half_rn(v.w));
    uint2 u;
    u.x = (uint32_t)h0 | ((uint32_t)h1 << 16);
    u.y = (uint32_t)h2 | ((uint32_t)h3 << 16);
    out[i] = u;
}

// ================= GEMM engine (4 warps, 64x64 warptile) =================
#define LOADFRAG_NT(aoff, boff, ks, buf)                                                \
    {                                                                                   \
        _Pragma("unroll")                                                               \
        for (int mi = 0; mi < 4; mi++)                                                  \
            LDMX4(af[buf][mi][0], af[buf][mi][1], af[buf][mi][2], af[buf][mi][3],       \
                  (aoff) + (uint32_t)(((wm2 * 64 + mi * 16 + l15) * 72 + lh * 8 + (ks) * 16) * 2)); \
        _Pragma("unroll")                                                               \
        for (int j2 = 0; j2 < 4; j2++)                                                  \
            LDMX4(bf[buf][j2][0], bf[buf][j2][1], bf[buf][j2][2], bf[buf][j2][3],       \
                  (boff) + (uint32_t)(((wn2 * 64 + j2 * 16 + l15) * 72 + lh * 8 + (ks) * 16) * 2)); \
    }

#define LOADFRAG_NN(aoff, boff, ks, buf)                                                \
    {                                                                                   \
        _Pragma("unroll")                                                               \
        for (int mi = 0; mi < 4; mi++)                                                  \
            LDMX4(af[buf][mi][0], af[buf][mi][1], af[buf][mi][2], af[buf][mi][3],       \
                  (aoff) + (uint32_t)(((wm2 * 64 + mi * 16 + l15) * 72 + lh * 8 + (ks) * 16) * 2)); \
        _Pragma("unroll")                                                               \
        for (int j2 = 0; j2 < 4; j2++)                                                  \
            LDMX4T(bf[buf][j2][0], bf[buf][j2][1], bf[buf][j2][2], bf[buf][j2][3],      \
                  (boff) + (uint32_t)((((ks) * 16 + l15) * 136 + wn2 * 64 + j2 * 16 + lh * 8) * 2)); \
    }

#define COMPUTE_BODY(LOADFRAG, MOP, B0A, B0B, B1A, B1B)                                 \
    {                                                                                   \
        uint32_t af[2][4][4], bf[2][4][4];                                              \
        LOADFRAG(aoff_, boff_, 0, 0);                                                   \
        _Pragma("unroll")                                                               \
        for (int ks = 0; ks < 4; ks++) {                                                \
            const int cur = ks & 1;                                                     \
            if (ks < 3) LOADFRAG(aoff_, boff_, ks + 1, cur ^ 1);                        \
            _Pragma("unroll")                                                           \
            for (int mi = 0; mi < 4; mi++) {                                            \
                _Pragma("unroll")                                                       \
                for (int j2 = 0; j2 < 4; j2++) {                                        \
                    MOP(acc[mi][2*j2],   af[cur][mi], bf[cur][j2][B0A], bf[cur][j2][B0B]); \
                    MOP(acc[mi][2*j2+1], af[cur][mi], bf[cur][j2][B1A], bf[cur][j2][B1B]); \
                }                                                                       \
            }                                                                           \
        }                                                                               \
    }

#define COMPUTE_NT_H() COMPUTE_BODY(LOADFRAG_NT, MMAH, 0, 2, 1, 3)
#define COMPUTE_NN_H() COMPUTE_BODY(LOADFRAG_NN, MMAH, 0, 1, 2, 3)

#define MAINLOOP(NTtiles, LOADFN, COMPUTE_MACRO)                                        \
    LOADFN(0, 0);                                                                       \
    LOADFN(1, 1);                                                                       \
    {                                                                                   \
        int cs = 0;                                                                     \
        for (int t = 0; t < (NTtiles); t++) {                                           \
            if (t + 2 < (NTtiles)) { CP_WAIT(1); } else { CP_WAIT(0); }                 \
            __syncthreads();                                                            \
            int ldst = cs + 2; if (ldst >= 3) ldst -= 3;                                \
            if (t + 2 < (NTtiles)) LOADFN(t + 2, ldst);                                 \
            const uint32_t aoff_ = sbase + (uint32_t)cs * STAGE_BYTES;                  \
            const uint32_t boff_ = aoff_ + A_STAGE_BYTES;                               \
            COMPUTE_MACRO();                                                            \
            cs = (cs == 2) ? 0 : cs + 1;                                                \
        }                                                                               \
    }

#define ACC_DECL                                                                        \
    float acc[4][8][4];                                                                 \
    _Pragma("unroll")                                                                   \
    for (int i = 0; i < 4; i++)                                                         \
        _Pragma("unroll")                                                               \
        for (int j = 0; j < 8; j++)                                                     \
            _Pragma("unroll")                                                           \
            for (int r = 0; r < 4; r++) acc[i][j][r] = 0.f;

// ---------------- projection GEMM: plain fp16, K=1024 ----------------
__global__ void __launch_bounds__(THREADS, 2)
proj_gemm(const __half* __restrict__ A,
          const __half* __restrict__ Wq, const __half* __restrict__ Wk,
          const __half* __restrict__ Wv,
          __half* __restrict__ Qo, __half* __restrict__ Ko,
          __half* __restrict__ Vo, int wsel_base)
{
    extern __shared__ char smem[];
    const uint32_t sbase = smem_u32(smem);

    const int wsel = wsel_base + (blockIdx.x >> 3);
    const __half* B = (wsel == 0) ? Wq : (wsel == 1) ? Wk : Wv;
    __half* Co = (wsel == 0) ? Qo : (wsel == 1) ? Ko : Vo;

    const int tid = threadIdx.x, lid = tid & 31, wid = tid >> 5;
    const int wm2 = wid & 1, wn2 = wid >> 1;
    const int row0 = blockIdx.y * BM, col0 = (blockIdx.x & 7) * BN;
    const int nT = DIM / BK;   // 16

    ACC_DECL;

    auto LOAD = [&](int t, int st) {
        const long kt = (long)t * BK;
        const uint32_t aoff = sbase + (uint32_t)st * STAGE_BYTES;
        const uint32_t boff = aoff + A_STAGE_BYTES;
        #pragma unroll
        for (int i = 0; i < 8; i++) {
            int idx = tid + i * THREADS;
            int row = idx >> 3, q = idx & 7;
            CPASYNC(aoff + (uint32_t)(row * 144 + q * 16),
                    A + (long)(row0 + row) * DIM + kt + q * 8);
            CPASYNC(boff + (uint32_t)(row * 144 + q * 16),
                    B + (long)(col0 + row) * DIM + kt + q * 8);
        }
        CP_COMMIT();
    };

    const int l15 = lid & 15, lh = lid >> 4;

    MAINLOOP(nT, LOAD, COMPUTE_NT_H);

    const int g = lid >> 2, tig = lid & 3;
    #pragma unroll
    for (int mi = 0; mi < 4; mi++) {
        #pragma unroll
        for (int j = 0; j < 8; j++) {
            const int c = col0 + wn2 * 64 + j * 8 + 2 * tig;
            #pragma unroll
            for (int s = 0; s < 2; s++) {
                const int r = row0 + wm2 * 64 + mi * 16 + g + s * 8;
                unsigned short h0 = __half_as_ushort(__float2half_rn(acc[mi][j][2*s]));
                unsigned short h1 = __half_as_ushort(__float2half_rn(acc[mi][j][2*s+1]));
                *reinterpret_cast<uint32_t*>(Co + (long)r * DIM + c) =
                    (uint32_t)h0 | ((uint32_t)h1 << 16);
            }
        }
    }
}

// ---------------- scores GEMM: plain fp16, K=1024, triangular grid, batched ----------------
__global__ void __launch_bounds__(THREADS, 2)
scores_gemm(const __half* __restrict__ Q, const __half* __restrict__ Kk,
            float* __restrict__ Sc, float alpha)
{
    extern __shared__ char smem[];
    const uint32_t sbase = smem_u32(smem);

    int t_lin = blockIdx.x;
    int by = (int)((sqrtf(8.f * t_lin + 1.f) - 1.f) * 0.5f);
    while ((by + 1) * (by + 2) / 2 <= t_lin) by++;
    while (by * (by + 1) / 2 > t_lin) by--;
    const int bx = t_lin - by * (by + 1) / 2;

    const __half* A = Q  + (long)blockIdx.z * SEQ * DIM;
    const __half* B = Kk + (long)blockIdx.z * SEQ * DIM;
    float* C = Sc + (long)blockIdx.z * SEQ * SEQ;

    const int tid = threadIdx.x, lid = tid & 31, wid = tid >> 5;
    const int wm2 = wid & 1, wn2 = wid >> 1;
    const int row0 = by * BM, col0 = bx * BN;
    const int nT = DIM / BK;   // 16

    ACC_DECL;

    auto LOAD = [&](int t, int st) {
        const long kt = (long)t * BK;
        const uint32_t aoff = sbase + (uint32_t)st * STAGE_BYTES;
        const uint32_t boff = aoff + A_STAGE_BYTES;
        #pragma unroll
        for (int i = 0; i < 8; i++) {
            int idx = tid + i * THREADS;
            int row = idx >> 3, q = idx & 7;
            CPASYNC(aoff + (uint32_t)(row * 144 + q * 16),
                    A + (long)(row0 + row) * DIM + kt + q * 8);
            CPASYNC(boff + (uint32_t)(row * 144 + q * 16),
                    B + (long)(col0 + row) * DIM + kt + q * 8);
        }
        CP_COMMIT();
    };

    const int l15 = lid & 15, lh = lid >> 4;

    MAINLOOP(nT, LOAD, COMPUTE_NT_H);

    const int g = lid >> 2, tig = lid & 3;
    #pragma unroll
    for (int mi = 0; mi < 4; mi++) {
        #pragma unroll
        for (int j = 0; j < 8; j++) {
            const int c = col0 + wn2 * 64 + j * 8 + 2 * tig;
            #pragma unroll
            for (int s = 0; s < 2; s++) {
                const int r = row0 + wm2 * 64 + mi * 16 + g + s * 8;
                float2 o = make_float2(acc[mi][j][2*s] * alpha, acc[mi][j][2*s+1] * alpha);
                *reinterpret_cast<float2*>(&C[(long)r * SEQ + c]) = o;
            }
        }
    }
}

// ---------------- PV GEMM: plain fp16 NN, causal-limited K, batched ----------------
__global__ void __launch_bounds__(THREADS, 2)
pv_gemm(const __half* __restrict__ P, const __half* __restrict__ V,
        float* __restrict__ Out)
{
    extern __shared__ char smem[];
    const uint32_t sbase = smem_u32(smem);

    const int by = gridDim.y - 1 - blockIdx.y;    // longest K first
    const __half* A = P + (long)blockIdx.z * SEQ * SEQ;
    const __half* B = V + (long)blockIdx.z * SEQ * DIM;
    float* C = Out + (long)blockIdx.z * SEQ * DIM;

    const int tid = threadIdx.x, lid = tid & 31, wid = tid >> 5;
    const int wm2 = wid & 1, wn2 = wid >> 1;
    const int row0 = by * BM, col0 = blockIdx.x * BN;
    const int nT = (by + 1) * BM / BK;            // 2*(by+1) >= 2

    ACC_DECL;

    auto LOAD = [&](int t, int st) {
        const long kt = (long)t * BK;
        const uint32_t aoff = sbase + (uint32_t)st * STAGE_BYTES;
        const uint32_t boff = aoff + A_STAGE_BYTES;
        #pragma unroll
        for (int i = 0; i < 8; i++) {
            int idx = tid + i * THREADS;
            int row = idx >> 3, q = idx & 7;
            CPASYNC(aoff + (uint32_t)(row * 144 + q * 16),
                    A + (long)(row0 + row) * SEQ + kt + q * 8);
            int kr = idx >> 4, c = (idx & 15) * 8;
            CPASYNC(boff + (uint32_t)(kr * 272 + c * 2),
                    B + (long)(kt + kr) * DIM + col0 + c);
        }
        CP_COMMIT();
    };

    const int l15 = lid & 15, lh = lid >> 4;

    MAINLOOP(nT, LOAD, COMPUTE_NN_H);

    const int g = lid >> 2, tig = lid & 3;
    #pragma unroll
    for (int mi = 0; mi < 4; mi++) {
        #pragma unroll
        for (int j = 0; j < 8; j++) {
            const int c = col0 + wn2 * 64 + j * 8 + 2 * tig;
            #pragma unroll
            for (int s = 0; s < 2; s++) {
                const int r = row0 + wm2 * 64 + mi * 16 + g + s * 8;
                float2 o = make_float2(acc[mi][j][2*s], acc[mi][j][2*s+1]);
                *reinterpret_cast<float2*>(&C[(long)r * DIM + c]) = o;
            }
        }
    }
}

// ---------------- softmax: single global read, fp32 scores -> plain fp16 P ----------------
__global__ __launch_bounds__(256)
void softmax_p2(const float* __restrict__ Sc, const int* __restrict__ mask,
                __half* __restrict__ Ph)
{
    __shared__ float e[SEQ];
    __shared__ float red[256];
    const int q = SEQ - 1 - blockIdx.x;   // longest rows first
    const int b = blockIdx.y, tid = threadIdx.x;
    const float* row = Sc + ((long)b * SEQ + q) * SEQ;
    const int* mk = mask + (long)b * SEQ;
    uint32_t* pr = reinterpret_cast<uint32_t*>(Ph + ((long)b * SEQ + q) * (long)SEQ);
    const int qe = ((q >> 7) + 1) << 7;    // block-aligned end

    // pass 1: single global read; cache raw (masked -> -inf) scores in smem, find max
    float mx = -CUDART_INF_F;
    for (int c = tid; c <= q; c += 256) {
        float v = mk[c] ? row[c] : -CUDART_INF_F;
        e[c] = v;
        mx = fmaxf(mx, v);
    }
    for (int c = q + 1 + tid; c < qe; c += 256) e[c] = -CUDART_INF_F;
    red[tid] = mx; __syncthreads();
    #pragma unroll
    for (int s = 128; s > 0; s >>= 1) {
        if (tid < s) red[tid] = fmaxf(red[tid], red[tid + s]);
        __syncthreads();
    }
    mx = red[0]; __syncthreads();

    // pass 2 (smem only): exp + sum
    float sum = 0.f;
    for (int c = tid; c < qe; c += 256) {
        float v = __expf(e[c] - mx);   // exp(-inf - mx) = 0
        e[c] = v;
        sum += v;
    }
    red[tid] = sum; __syncthreads();
    #pragma unroll
    for (int s = 128; s > 0; s >>= 1) {
        if (tid < s) red[tid] += red[tid + s];
        __syncthreads();
    }
    const float inv = 1.f / red[0];
    __syncthreads();

    const int npair = qe >> 1;
    for (int t2 = tid; t2 < npair; t2 += 256) {
        unsigned short h0 = __half_as_ushort(__float2half_rn(e[2 * t2]     * inv));
        unsigned short h1 = __half_as_ushort(__float2half_rn(e[2 * t2 + 1] * inv));
        pr[t2] = (uint32_t)h0 | ((uint32_t)h1 << 16);
    }
}

// ---------------- host ----------------
extern "C" void kernel_launch(void* const* d_in, const int* in_sizes, int n_in,
                              void* d_out, int out_size)
{
    const float* x    = (const float*)d_in[0];
    const int*   mask = (const int*)  d_in[1];
    const float* Wq   = (const float*)d_in[2];
    const float* Wk   = (const float*)d_in[3];
    const float* Wv   = (const float*)d_in[4];
    float* out = (float*)d_out;

    __half *xp, *wqp, *wkp, *wvp, *qp, *kp, *vp, *pp;
    float* sp;
    cudaGetSymbolAddress((void**)&xp,  g_xh);
    cudaGetSymbolAddress((void**)&wqp, g_Wqh);
    cudaGetSymbolAddress((void**)&wkp, g_Wkh);
    cudaGetSymbolAddress((void**)&wvp, g_Wvh);
    cudaGetSymbolAddress((void**)&qp,  g_Qh);
    cudaGetSymbolAddress((void**)&kp,  g_Kh);
    cudaGetSymbolAddress((void**)&vp,  g_Vh);
    cudaGetSymbolAddress((void**)&sp,  g_S);
    cudaGetSymbolAddress((void**)&pp,  g_Ph);

    static cudaStream_t s2 = nullptr;
    static cudaEvent_t ev0 = nullptr, ev1 = nullptr;
    static bool init_done = false;
    if (!init_done) {
        cudaFuncSetAttribute(proj_gemm,   cudaFuncAttributeMaxDynamicSharedMemorySize, SMEM_TOTAL);
        cudaFuncSetAttribute(scores_gemm, cudaFuncAttributeMaxDynamicSharedMemorySize, SMEM_TOTAL);
        cudaFuncSetAttribute(pv_gemm,     cudaFuncAttributeMaxDynamicSharedMemorySize, SMEM_TOTAL);
        cudaStreamCreateWithFlags(&s2, cudaStreamNonBlocking);
        cudaEventCreateWithFlags(&ev0, cudaEventDisableTiming);
        cudaEventCreateWithFlags(&ev1, cudaEventDisableTiming);
        init_done = true;
    }

    const long nx4 = (long)BATCH * SEQ * DIM / 4;
    const long nw4 = (long)DIM * DIM / 4;
    convert_f16<<<(unsigned)((nx4 + 255) / 256), 256>>>((const float4*)x, (uint2*)xp, nx4);
    convert_w3<<<dim3((unsigned)((nw4 + 255) / 256), 3), 256>>>(
        (const float4*)Wq, (const float4*)Wk, (const float4*)Wv,
        (uint2*)wqp, (uint2*)wkp, (uint2*)wvp, nw4);

    // fork: V projection on side stream, overlapping scores + softmax
    cudaEventRecord(ev0, 0);
    cudaStreamWaitEvent(s2, ev0, 0);
    dim3 gV(8, (BATCH * SEQ) / BM, 1);
    proj_gemm<<<gV, THREADS, SMEM_TOTAL, s2>>>(xp, wqp, wkp, wvp, qp, kp, vp, 2);
    cudaEventRecord(ev1, s2);

    // main: QK projections
    dim3 gQK(16, (BATCH * SEQ) / BM, 1);
    proj_gemm<<<gQK, THREADS, SMEM_TOTAL>>>(xp, wqp, wkp, wvp, qp, kp, vp, 0);

    // scores: plain fp16, triangular-packed grid, batched
    dim3 gS(136, 1, BATCH);
    scores_gemm<<<gS, THREADS, SMEM_TOTAL>>>(qp, kp, sp, 1.f / 32.f);

    // softmax -> plain fp16 P (single global read)
    softmax_p2<<<dim3(SEQ, BATCH), 256>>>(sp, mask, pp);

    // join: PV needs V
    cudaStreamWaitEvent(0, ev1, 0);
    dim3 gO(DIM / BN, SEQ / BM, BATCH);
    pv_gemm<<<gO, THREADS, SMEM_TOTAL>>>(pp, vp, out);
}